// round 6
// baseline (speedup 1.0000x reference)
#include <cuda_runtime.h>
#include <cstdint>

#define T_STEPS 256
#define BATCH   64
#define HID     512
#define OUTD    4

#define CLUSTER 8          // CTAs per cluster
#define RPC     4          // batch rows per cluster
#define CPC     64         // hidden columns per CTA
#define CHW     68         // padded chunk width (64 data + 4 pad)

// Global scratch (no cudaMalloc allowed)
__device__ __align__(16) float g_xw[T_STEPS * BATCH * HID];   // [T][B][H]

__device__ __forceinline__ uint32_t smem_u32(const void* p) {
    uint32_t a;
    asm("{ .reg .u64 t; cvta.to.shared.u64 t, %1; cvt.u32.u64 %0, t; }"
        : "=r"(a) : "l"(p));
    return a;
}
__device__ __forceinline__ void st_dsmem_f32(uint32_t laddr, int crank, float v) {
    uint32_t raddr;
    asm volatile("mapa.shared::cluster.u32 %0, %1, %2;"
                 : "=r"(raddr) : "r"(laddr), "r"(crank));
    asm volatile("st.shared::cluster.f32 [%0], %1;"
                 :: "r"(raddr), "f"(v) : "memory");
}
__device__ __forceinline__ unsigned long long fma_f32x2(unsigned long long a,
                                                        unsigned long long b,
                                                        unsigned long long c) {
    unsigned long long d;
    asm("fma.rn.f32x2 %0, %1, %2, %3;" : "=l"(d) : "l"(a), "l"(b), "l"(c));
    return d;
}
__device__ __forceinline__ float f32x2_hsum(unsigned long long a,
                                            unsigned long long b) {
    unsigned long long s;
    asm("add.rn.f32x2 %0, %1, %2;" : "=l"(s) : "l"(a), "l"(b));
    unsigned int lo, hi;
    asm("mov.b64 {%0, %1}, %2;" : "=r"(lo), "=r"(hi) : "l"(s));
    return __uint_as_float(lo) + __uint_as_float(hi);
}

// Accurate even under --use_fast_math (expf -> __expf ~2^-21 rel error).
__device__ __forceinline__ float tanh_accurate(float z) {
    return 1.0f - 2.0f / (expf(2.0f * z) + 1.0f);
}

// ---------------------------------------------------------------------------
// Kernel 1: g_xw[t][b][:] = emb[x[b][t]] @ W_ih^T + b_ih
// 128x128 tile, BK=8, 256 threads, 8x8 microtile, register-prefetch pipeline.
// ---------------------------------------------------------------------------
__global__ void __launch_bounds__(256)
proj_kernel(const int* __restrict__ x,
            const float* __restrict__ emb,
            const float* __restrict__ W_ih,
            const float* __restrict__ b_ih)
{
    __shared__ float As[8][128];
    __shared__ float Bs[8][128];
    __shared__ int   idx[128];

    const int tid = threadIdx.x;
    const int m0 = blockIdx.y * 128;   // row = b*T + t
    const int j0 = blockIdx.x * 128;   // hidden column

    if (tid < 128) idx[tid] = x[m0 + tid];
    __syncthreads();

    const int lrow = tid >> 1;         // 0..127
    const int lq   = tid & 1;          // k half (0 or 4)
    const int ty = tid >> 4;           // 0..15 -> rows 8*ty..
    const int tx = tid & 15;           // 0..15 -> cols 8*tx..

    const size_t arow = (size_t)idx[lrow] * HID;
    const size_t brow = (size_t)(j0 + lrow) * HID;

    float acc[8][8];
#pragma unroll
    for (int i = 0; i < 8; ++i)
#pragma unroll
        for (int jc = 0; jc < 8; ++jc) acc[i][jc] = 0.0f;

    float4 av = *(const float4*)(emb  + arow + 4 * lq);
    float4 bv = *(const float4*)(W_ih + brow + 4 * lq);

    for (int k0 = 0; k0 < HID; k0 += 8) {
        As[4*lq+0][lrow] = av.x; As[4*lq+1][lrow] = av.y;
        As[4*lq+2][lrow] = av.z; As[4*lq+3][lrow] = av.w;
        Bs[4*lq+0][lrow] = bv.x; Bs[4*lq+1][lrow] = bv.y;
        Bs[4*lq+2][lrow] = bv.z; Bs[4*lq+3][lrow] = bv.w;
        __syncthreads();

        if (k0 + 8 < HID) {
            av = *(const float4*)(emb  + arow + k0 + 8 + 4 * lq);
            bv = *(const float4*)(W_ih + brow + k0 + 8 + 4 * lq);
        }

#pragma unroll
        for (int k = 0; k < 8; ++k) {
            float a[8], b[8];
            *(float4*)(a)     = *(const float4*)(&As[k][8 * ty]);
            *(float4*)(a + 4) = *(const float4*)(&As[k][8 * ty + 4]);
            *(float4*)(b)     = *(const float4*)(&Bs[k][8 * tx]);
            *(float4*)(b + 4) = *(const float4*)(&Bs[k][8 * tx + 4]);
#pragma unroll
            for (int i = 0; i < 8; ++i)
#pragma unroll
                for (int jc = 0; jc < 8; ++jc)
                    acc[i][jc] += a[i] * b[jc];
        }
        __syncthreads();
    }

    float bi[8];
    *(float4*)(bi)     = *(const float4*)(b_ih + j0 + 8 * tx);
    *(float4*)(bi + 4) = *(const float4*)(b_ih + j0 + 8 * tx + 4);

#pragma unroll
    for (int i = 0; i < 8; ++i) {
        int m = m0 + 8 * ty + i;
        int b = m >> 8;      // T = 256
        int t = m & 255;
        float* dst = &g_xw[((size_t)t * BATCH + b) * HID + j0 + 8 * tx];
        float4 v0, v1;
        v0.x = acc[i][0] + bi[0]; v0.y = acc[i][1] + bi[1];
        v0.z = acc[i][2] + bi[2]; v0.w = acc[i][3] + bi[3];
        v1.x = acc[i][4] + bi[4]; v1.y = acc[i][5] + bi[5];
        v1.z = acc[i][6] + bi[6]; v1.w = acc[i][7] + bi[7];
        *(float4*)(dst)     = v0;
        *(float4*)(dst + 4) = v1;
    }
}

// ---------------------------------------------------------------------------
// Kernel 2: recurrence + FC. 16 clusters x 8 CTAs x 512 threads.
// Thread (j = tid>>3, kc = tid&7): W_hh[j0+j][64kc..+63] packed f32x2 in regs.
// h stored in padded chunk layout hs[buf][row][chunk][68] (conflict-free for
// the kc-varying loads). Partials reduced via 3x shfl.bfly within the 8-lane
// kc group; every lane then pushes the (redundant) result to peer rank==kc.
// One barrier.cluster per step; no __syncthreads in the loop.
// ---------------------------------------------------------------------------
__global__ void __cluster_dims__(CLUSTER, 1, 1) __launch_bounds__(512, 1)
rec_kernel(const float* __restrict__ W_hh,
           const float* __restrict__ b_hh,
           const float* __restrict__ W_fc,
           const float* __restrict__ b_fc,
           float* __restrict__ out)
{
    __shared__ float hs[2][RPC][8][CHW];     // padded h, double-buffered

    const int tid  = threadIdx.x;
    const int rank = blockIdx.x & (CLUSTER - 1);
    const int cl   = blockIdx.x / CLUSTER;
    const int r0 = cl * RPC;
    const int j0 = rank * CPC;

    const int j  = tid >> 3;    // 0..63: column within slice
    const int kc = tid & 7;     // k chunk == destination peer rank

    // W_hh slice packed as f32x2 pairs (64 floats = 32 u64).
    unsigned long long wp[32];
    {
        const float* wrow = W_hh + (size_t)(j0 + j) * HID + kc * 64;
#pragma unroll
        for (int q = 0; q < 16; ++q) {
            ulonglong2 v = *(const ulonglong2*)(wrow + 4 * q);
            wp[2*q]   = v.x;
            wp[2*q+1] = v.y;
        }
    }
    const float bhh = b_hh[j0 + j];
    const int dst_chunk = (j0 + j) >> 6;
    const int dst_off   = (j0 + j) & 63;

    // h0 = 0 in buffer 0.
    for (int i = tid; i < RPC * 8 * CHW; i += 512)
        (&hs[0][0][0][0])[i] = 0.0f;
    __syncthreads();

    for (int p = 1; p <= T_STEPS; ++p) {
        const int rb = (p - 1) & 1;
        const int wb = p & 1;

        // xw for this step (all lanes; redundant across kc group).
        float xwv[RPC];
#pragma unroll
        for (int r = 0; r < RPC; ++r)
            xwv[r] = g_xw[((size_t)(p - 1) * BATCH + (r0 + r)) * HID + j0 + j];

        float hval[RPC];
#pragma unroll
        for (int r = 0; r < RPC; ++r) {
            const ulonglong2* hrow = (const ulonglong2*)(&hs[rb][r][kc][0]);
            unsigned long long a0 = 0ull, a1 = 0ull;
#pragma unroll
            for (int q = 0; q < 8; ++q) {
                ulonglong2 h0 = hrow[2*q];
                ulonglong2 h1 = hrow[2*q+1];
                a0 = fma_f32x2(h0.x, wp[4*q+0], a0);
                a1 = fma_f32x2(h0.y, wp[4*q+1], a1);
                a0 = fma_f32x2(h1.x, wp[4*q+2], a0);
                a1 = fma_f32x2(h1.y, wp[4*q+3], a1);
            }
            float part = f32x2_hsum(a0, a1);
            // butterfly reduce over the 8-lane kc group (all lanes get sum)
            part += __shfl_xor_sync(0xFFFFFFFFu, part, 1);
            part += __shfl_xor_sync(0xFFFFFFFFu, part, 2);
            part += __shfl_xor_sync(0xFFFFFFFFu, part, 4);
            hval[r] = tanh_accurate(part + bhh + xwv[r]);
        }

        // Push to peer rank == kc (each of the 8 redundant lanes covers one peer).
#pragma unroll
        for (int r = 0; r < RPC; ++r) {
            uint32_t laddr = smem_u32(&hs[wb][r][dst_chunk][dst_off]);
            st_dsmem_f32(laddr, kc, hval[r]);
        }

        // One cluster barrier per step (release pushes / acquire peers').
        asm volatile("barrier.cluster.arrive.aligned;" ::: "memory");
        asm volatile("barrier.cluster.wait.aligned;"   ::: "memory");
    }

    // FC from local smem: h_T lives in buffer (T_STEPS & 1) = 0.
    // Warp w: row r = w>>2, output o = w&3.
    if (rank == 0) {
        const int w    = tid >> 5;
        const int lane = tid & 31;
        const int r = w >> 2;
        const int o = w & 3;
        float s = 0.0f;
        const float* wf = W_fc + (size_t)o * HID;
#pragma unroll
        for (int k = lane; k < HID; k += 32)
            s += hs[0][r][k >> 6][k & 63] * wf[k];
#pragma unroll
        for (int sh = 16; sh > 0; sh >>= 1)
            s += __shfl_xor_sync(0xFFFFFFFFu, s, sh);
        if (lane == 0)
            out[(r0 + r) * OUTD + o] = s + b_fc[o];
    }
}

extern "C" void kernel_launch(void* const* d_in, const int* in_sizes, int n_in,
                              void* d_out, int out_size)
{
    const int*   x    = (const int*)  d_in[0];
    const float* emb  = (const float*)d_in[1];
    const float* W_ih = (const float*)d_in[2];
    const float* W_hh = (const float*)d_in[3];
    const float* b_ih = (const float*)d_in[4];
    const float* b_hh = (const float*)d_in[5];
    const float* W_fc = (const float*)d_in[6];
    const float* b_fc = (const float*)d_in[7];
    float* out = (float*)d_out;
    (void)in_sizes; (void)n_in; (void)out_size;

    proj_kernel<<<dim3(HID / 128, (BATCH * T_STEPS) / 128), 256>>>(x, emb, W_ih, b_ih);
    rec_kernel<<<(BATCH / RPC) * CLUSTER, 512>>>(W_hh, b_hh, W_fc, b_fc, out);
}

// round 7
// speedup vs baseline: 1.3632x; 1.3632x over previous
#include <cuda_runtime.h>
#include <cstdint>

#define T_STEPS 256
#define BATCH   64
#define HID     512
#define OUTD    4

#define CLUSTER 8          // CTAs per cluster
#define RPC     4          // batch rows per cluster
#define CPC     64         // hidden columns per CTA

// Global scratch (no cudaMalloc allowed)
__device__ __align__(16) float g_xw[T_STEPS * BATCH * HID];   // [T][B][H]

__device__ __forceinline__ uint32_t smem_u32(const void* p) {
    uint32_t a;
    asm("{ .reg .u64 t; cvta.to.shared.u64 t, %1; cvt.u32.u64 %0, t; }"
        : "=r"(a) : "l"(p));
    return a;
}
__device__ __forceinline__ uint32_t mapa32(uint32_t a, int r) {
    uint32_t ra;
    asm("mapa.shared::cluster.u32 %0, %1, %2;" : "=r"(ra) : "r"(a), "r"(r));
    return ra;
}
__device__ __forceinline__ void mbar_init(uint32_t a, uint32_t cnt) {
    asm volatile("mbarrier.init.shared.b64 [%0], %1;" :: "r"(a), "r"(cnt) : "memory");
}
__device__ __forceinline__ void arrive_tx_remote(uint32_t rm, uint32_t bytes) {
    asm volatile("mbarrier.arrive.expect_tx.release.cluster.shared::cluster.b64 _, [%0], %1;"
                 :: "r"(rm), "r"(bytes) : "memory");
}
__device__ __forceinline__ void bulk_dsmem(uint32_t rdst, uint32_t lsrc,
                                           uint32_t bytes, uint32_t rm) {
    asm volatile("cp.async.bulk.shared::cluster.shared::cta.mbarrier::complete_tx::bytes "
                 "[%0], [%1], %2, [%3];"
                 :: "r"(rdst), "r"(lsrc), "r"(bytes), "r"(rm) : "memory");
}
__device__ __forceinline__ void mbar_wait(uint32_t a, uint32_t parity) {
    asm volatile("{\n\t.reg .pred P;\n\t"
                 "WL%=:\n\t"
                 "mbarrier.try_wait.parity.acquire.cluster.shared::cta.b64 P, [%0], %1;\n\t"
                 "@P bra WD%=;\n\t"
                 "bra WL%=;\n\t"
                 "WD%=:\n\t}"
                 :: "r"(a), "r"(parity) : "memory");
}

// Accurate even under --use_fast_math (expf -> __expf ~2^-21 rel error).
__device__ __forceinline__ float tanh_accurate(float z) {
    return 1.0f - 2.0f / (expf(2.0f * z) + 1.0f);
}

// ---------------------------------------------------------------------------
// Kernel 1: g_xw[t][b][:] = emb[x[b][t]] @ W_ih^T + b_ih
// 128x128 tile, BK=8, 256 threads, 8x8 microtile, register-prefetch pipeline.
// ---------------------------------------------------------------------------
__global__ void __launch_bounds__(256)
proj_kernel(const int* __restrict__ x,
            const float* __restrict__ emb,
            const float* __restrict__ W_ih,
            const float* __restrict__ b_ih)
{
    __shared__ float As[8][128];
    __shared__ float Bs[8][128];
    __shared__ int   idx[128];

    const int tid = threadIdx.x;
    const int m0 = blockIdx.y * 128;
    const int j0 = blockIdx.x * 128;

    if (tid < 128) idx[tid] = x[m0 + tid];
    __syncthreads();

    const int lrow = tid >> 1;
    const int lq   = tid & 1;
    const int ty = tid >> 4;
    const int tx = tid & 15;

    const size_t arow = (size_t)idx[lrow] * HID;
    const size_t brow = (size_t)(j0 + lrow) * HID;

    float acc[8][8];
#pragma unroll
    for (int i = 0; i < 8; ++i)
#pragma unroll
        for (int jc = 0; jc < 8; ++jc) acc[i][jc] = 0.0f;

    float4 av = *(const float4*)(emb  + arow + 4 * lq);
    float4 bv = *(const float4*)(W_ih + brow + 4 * lq);

    for (int k0 = 0; k0 < HID; k0 += 8) {
        As[4*lq+0][lrow] = av.x; As[4*lq+1][lrow] = av.y;
        As[4*lq+2][lrow] = av.z; As[4*lq+3][lrow] = av.w;
        Bs[4*lq+0][lrow] = bv.x; Bs[4*lq+1][lrow] = bv.y;
        Bs[4*lq+2][lrow] = bv.z; Bs[4*lq+3][lrow] = bv.w;
        __syncthreads();

        if (k0 + 8 < HID) {
            av = *(const float4*)(emb  + arow + k0 + 8 + 4 * lq);
            bv = *(const float4*)(W_ih + brow + k0 + 8 + 4 * lq);
        }

#pragma unroll
        for (int k = 0; k < 8; ++k) {
            float a[8], b[8];
            *(float4*)(a)     = *(const float4*)(&As[k][8 * ty]);
            *(float4*)(a + 4) = *(const float4*)(&As[k][8 * ty + 4]);
            *(float4*)(b)     = *(const float4*)(&Bs[k][8 * tx]);
            *(float4*)(b + 4) = *(const float4*)(&Bs[k][8 * tx + 4]);
#pragma unroll
            for (int i = 0; i < 8; ++i)
#pragma unroll
                for (int jc = 0; jc < 8; ++jc)
                    acc[i][jc] += a[i] * b[jc];
        }
        __syncthreads();
    }

    float bi[8];
    *(float4*)(bi)     = *(const float4*)(b_ih + j0 + 8 * tx);
    *(float4*)(bi + 4) = *(const float4*)(b_ih + j0 + 8 * tx + 4);

#pragma unroll
    for (int i = 0; i < 8; ++i) {
        int m = m0 + 8 * ty + i;
        int b = m >> 8;      // T = 256
        int t = m & 255;
        float* dst = &g_xw[((size_t)t * BATCH + b) * HID + j0 + 8 * tx];
        float4 v0, v1;
        v0.x = acc[i][0] + bi[0]; v0.y = acc[i][1] + bi[1];
        v0.z = acc[i][2] + bi[2]; v0.w = acc[i][3] + bi[3];
        v1.x = acc[i][4] + bi[4]; v1.y = acc[i][5] + bi[5];
        v1.z = acc[i][6] + bi[6]; v1.w = acc[i][7] + bi[7];
        *(float4*)(dst)     = v0;
        *(float4*)(dst + 4) = v1;
    }
}

// ---------------------------------------------------------------------------
// Kernel 2: recurrence + FC. 16 clusters x 8 CTAs x 512 threads.
// h layout hs[buf][srcRank][row][64]: peer pushes are contiguous 1KB blocks.
// Exchange = 8x cp.async.bulk (1KB) to peers with mbarrier complete_tx;
// per-step sync = one mbarrier parity wait (8 arrivals + 8KB tx). No
// barrier.cluster in the loop.
// ---------------------------------------------------------------------------
#define RNN_STEP(T, RB, WB, PHVAR, DOWAIT)                                    \
do {                                                                          \
    float xwv = 0.0f;                                                         \
    if (tid < 256)                                                            \
        xwv = g_xw[((size_t)(T) * BATCH + (r0 + rr)) * HID + j0 + jj];        \
    if (DOWAIT) { mbar_wait(barA + 8 * (RB), PHVAR); PHVAR ^= 1u; }           \
    _Pragma("unroll")                                                         \
    for (int r = 0; r < RPC; ++r) {                                           \
        const float4* hrow = (const float4*)(&hs[RB][kc][r][0]);              \
        float a0 = 0.0f, a1 = 0.0f;                                           \
        _Pragma("unroll")                                                     \
        for (int q = 0; q < 8; ++q) {                                         \
            float4 h0 = hrow[2*q];                                            \
            float4 h1 = hrow[2*q+1];                                          \
            a0 += h0.x * wreg[8*q+0] + h0.y * wreg[8*q+1]                     \
                + h0.z * wreg[8*q+2] + h0.w * wreg[8*q+3];                    \
            a1 += h1.x * wreg[8*q+4] + h1.y * wreg[8*q+5]                     \
                + h1.z * wreg[8*q+6] + h1.w * wreg[8*q+7];                    \
        }                                                                     \
        psum[r][kc][j] = a0 + a1;                                             \
    }                                                                         \
    __syncthreads();                                                          \
    if (tid < 256) {                                                          \
        float z = bhh + xwv;                                                  \
        _Pragma("unroll")                                                     \
        for (int c = 0; c < 8; ++c) z += psum[rr][c][jj];                     \
        stage[WB][rr][jj] = tanh_accurate(z);                                 \
    }                                                                         \
    __syncthreads();                                                          \
    if (tid < CLUSTER) {                                                      \
        asm volatile("fence.proxy.async.shared::cta;" ::: "memory");          \
        uint32_t rm   = mapa32(barA + 8 * (WB), tid);                         \
        uint32_t rdst = mapa32(hsA + ((WB) * 8 + rank) * 1024, tid);          \
        arrive_tx_remote(rm, 1024);                                           \
        bulk_dsmem(rdst, stgA + (WB) * 1024, 1024, rm);                       \
    }                                                                         \
} while (0)

__global__ void __cluster_dims__(CLUSTER, 1, 1) __launch_bounds__(512, 1)
rec_kernel(const float* __restrict__ W_hh,
           const float* __restrict__ b_hh,
           const float* __restrict__ W_fc,
           const float* __restrict__ b_fc,
           float* __restrict__ out)
{
    __shared__ __align__(16) float hs[2][CLUSTER][RPC][64];   // 16 KB
    __shared__ __align__(16) float psum[RPC][8][64];          // 8 KB
    __shared__ __align__(16) float stage[2][RPC][64];         // 2 KB
    __shared__ __align__(8)  unsigned long long mbar[2];

    const int tid  = threadIdx.x;
    const int rank = blockIdx.x & (CLUSTER - 1);
    const int cl   = blockIdx.x / CLUSTER;
    const int r0 = cl * RPC;
    const int j0 = rank * CPC;

    const int j  = tid & 63;    // compute: column within slice
    const int kc = tid >> 6;    // compute: 64-wide k chunk (0..7)
    const int rr = tid >> 6;    // reduce (tid<256): row 0..3
    const int jj = tid & 63;    // reduce: column

    const uint32_t barA = smem_u32(mbar);
    const uint32_t hsA  = smem_u32(hs);
    const uint32_t stgA = smem_u32(stage);

    // W_hh slice to registers (reused 256 steps x 4 rows)
    float wreg[64];
    {
        const float* wrow = W_hh + (size_t)(j0 + j) * HID + kc * 64;
#pragma unroll
        for (int q = 0; q < 16; ++q) {
            float4 v = *(const float4*)(wrow + 4 * q);
            wreg[4*q+0] = v.x; wreg[4*q+1] = v.y;
            wreg[4*q+2] = v.z; wreg[4*q+3] = v.w;
        }
    }
    const float bhh = b_hh[j0 + jj];

    // Init: barriers (8 arrivals/phase) + h0 = 0.
    if (tid == 0) { mbar_init(barA, CLUSTER); mbar_init(barA + 8, CLUSTER); }
    for (int i = tid; i < CLUSTER * RPC * 64; i += 512)
        (&hs[0][0][0][0])[i] = 0.0f;
    __syncthreads();
    // Peers' barriers must be initialized before any remote arrive.
    asm volatile("barrier.cluster.arrive.aligned;" ::: "memory");
    asm volatile("barrier.cluster.wait.aligned;"   ::: "memory");

    uint32_t ph0 = 0, ph1 = 0;

    // Step p=1: rb=0 (local zeros, no wait), wb=1.
    RNN_STEP(0, 0, 1, ph0, false);
    // Step p=2: rb=1, wb=0.
    RNN_STEP(1, 1, 0, ph1, true);
    // Steps 3..256 in pairs.
    for (int q = 1; q < 128; ++q) {
        RNN_STEP(2 * q,     0, 1, ph0, true);   // odd step  p=2q+1
        RNN_STEP(2 * q + 1, 1, 0, ph1, true);   // even step p=2q+2
    }

    // Consume the step-256 pushes (buffer 0) — all ranks, all inbound tx done.
    mbar_wait(barA, ph0);

    // FC: h_T in hs[0]; h[r][k] = hs[0][k>>6][r][k&63]. Warp w: r=w>>2, o=w&3.
    if (rank == 0) {
        const int w    = tid >> 5;
        const int lane = tid & 31;
        const int r = w >> 2;
        const int o = w & 3;
        float s = 0.0f;
        const float* wf = W_fc + (size_t)o * HID;
#pragma unroll
        for (int k = lane; k < HID; k += 32)
            s += hs[0][k >> 6][r][k & 63] * wf[k];
#pragma unroll
        for (int sh = 16; sh > 0; sh >>= 1)
            s += __shfl_xor_sync(0xFFFFFFFFu, s, sh);
        if (lane == 0)
            out[(r0 + r) * OUTD + o] = s + b_fc[o];
    }

    // Cluster-wide quiesce before exit (DSMEM lifetime).
    asm volatile("barrier.cluster.arrive.aligned;" ::: "memory");
    asm volatile("barrier.cluster.wait.aligned;"   ::: "memory");
}

extern "C" void kernel_launch(void* const* d_in, const int* in_sizes, int n_in,
                              void* d_out, int out_size)
{
    const int*   x    = (const int*)  d_in[0];
    const float* emb  = (const float*)d_in[1];
    const float* W_ih = (const float*)d_in[2];
    const float* W_hh = (const float*)d_in[3];
    const float* b_ih = (const float*)d_in[4];
    const float* b_hh = (const float*)d_in[5];
    const float* W_fc = (const float*)d_in[6];
    const float* b_fc = (const float*)d_in[7];
    float* out = (float*)d_out;
    (void)in_sizes; (void)n_in; (void)out_size;

    proj_kernel<<<dim3(HID / 128, (BATCH * T_STEPS) / 128), 256>>>(x, emb, W_ih, b_ih);
    rec_kernel<<<(BATCH / RPC) * CLUSTER, 512>>>(W_hh, b_hh, W_fc, b_fc, out);
}

// round 9
// speedup vs baseline: 1.6067x; 1.1786x over previous
#include <cuda_runtime.h>
#include <cstdint>

#define T_STEPS 256
#define BATCH   64
#define HID     512
#define OUTD    4

#define CLUSTER 8          // CTAs per cluster
#define RPC     4          // batch rows per cluster
#define CPC     64         // hidden columns per CTA

// Global scratch (no cudaMalloc allowed)
__device__ __align__(16) float g_xw[T_STEPS * BATCH * HID];   // [T][B][H]

__device__ __forceinline__ uint32_t smem_u32(const void* p) {
    uint32_t a;
    asm("{ .reg .u64 t; cvta.to.shared.u64 t, %1; cvt.u32.u64 %0, t; }"
        : "=r"(a) : "l"(p));
    return a;
}
__device__ __forceinline__ void st_dsmem_f32(uint32_t laddr, int crank, float v) {
    uint32_t raddr;
    asm volatile("mapa.shared::cluster.u32 %0, %1, %2;"
                 : "=r"(raddr) : "r"(laddr), "r"(crank));
    asm volatile("st.shared::cluster.f32 [%0], %1;"
                 :: "r"(raddr), "f"(v) : "memory");
}
__device__ __forceinline__ unsigned long long fma2(unsigned long long a,
                                                   unsigned long long b,
                                                   unsigned long long c) {
    unsigned long long d;
    asm("fma.rn.f32x2 %0, %1, %2, %3;" : "=l"(d) : "l"(a), "l"(b), "l"(c));
    return d;
}
__device__ __forceinline__ float f32x2_hsum(unsigned long long a,
                                            unsigned long long b) {
    unsigned long long s;
    asm("add.rn.f32x2 %0, %1, %2;" : "=l"(s) : "l"(a), "l"(b));
    unsigned int lo, hi;
    asm("mov.b64 {%0, %1}, %2;" : "=r"(lo), "=r"(hi) : "l"(s));
    return __uint_as_float(lo) + __uint_as_float(hi);
}

// Accurate even under --use_fast_math (expf -> __expf ~2^-21 rel error).
__device__ __forceinline__ float tanh_accurate(float z) {
    return 1.0f - 2.0f / (expf(2.0f * z) + 1.0f);
}

// ---------------------------------------------------------------------------
// Kernel 1: g_xw[t][b][:] = emb[x[b][t]] @ W_ih^T + b_ih
// 128x128 tile, BK=8, 256 threads, 8x8 microtile, register-prefetch pipeline.
// ---------------------------------------------------------------------------
__global__ void __launch_bounds__(256)
proj_kernel(const int* __restrict__ x,
            const float* __restrict__ emb,
            const float* __restrict__ W_ih,
            const float* __restrict__ b_ih)
{
    __shared__ float As[8][128];
    __shared__ float Bs[8][128];
    __shared__ int   idx[128];

    const int tid = threadIdx.x;
    const int m0 = blockIdx.y * 128;
    const int j0 = blockIdx.x * 128;

    if (tid < 128) idx[tid] = x[m0 + tid];
    __syncthreads();

    const int lrow = tid >> 1;
    const int lq   = tid & 1;
    const int ty = tid >> 4;
    const int tx = tid & 15;

    const size_t arow = (size_t)idx[lrow] * HID;
    const size_t brow = (size_t)(j0 + lrow) * HID;

    float acc[8][8];
#pragma unroll
    for (int i = 0; i < 8; ++i)
#pragma unroll
        for (int jc = 0; jc < 8; ++jc) acc[i][jc] = 0.0f;

    float4 av = *(const float4*)(emb  + arow + 4 * lq);
    float4 bv = *(const float4*)(W_ih + brow + 4 * lq);

    for (int k0 = 0; k0 < HID; k0 += 8) {
        As[4*lq+0][lrow] = av.x; As[4*lq+1][lrow] = av.y;
        As[4*lq+2][lrow] = av.z; As[4*lq+3][lrow] = av.w;
        Bs[4*lq+0][lrow] = bv.x; Bs[4*lq+1][lrow] = bv.y;
        Bs[4*lq+2][lrow] = bv.z; Bs[4*lq+3][lrow] = bv.w;
        __syncthreads();

        if (k0 + 8 < HID) {
            av = *(const float4*)(emb  + arow + k0 + 8 + 4 * lq);
            bv = *(const float4*)(W_ih + brow + k0 + 8 + 4 * lq);
        }

#pragma unroll
        for (int k = 0; k < 8; ++k) {
            float a[8], b[8];
            *(float4*)(a)     = *(const float4*)(&As[k][8 * ty]);
            *(float4*)(a + 4) = *(const float4*)(&As[k][8 * ty + 4]);
            *(float4*)(b)     = *(const float4*)(&Bs[k][8 * tx]);
            *(float4*)(b + 4) = *(const float4*)(&Bs[k][8 * tx + 4]);
#pragma unroll
            for (int i = 0; i < 8; ++i)
#pragma unroll
                for (int jc = 0; jc < 8; ++jc)
                    acc[i][jc] += a[i] * b[jc];
        }
        __syncthreads();
    }

    float bi[8];
    *(float4*)(bi)     = *(const float4*)(b_ih + j0 + 8 * tx);
    *(float4*)(bi + 4) = *(const float4*)(b_ih + j0 + 8 * tx + 4);

#pragma unroll
    for (int i = 0; i < 8; ++i) {
        int m = m0 + 8 * ty + i;
        int b = m >> 8;      // T = 256
        int t = m & 255;
        float* dst = &g_xw[((size_t)t * BATCH + b) * HID + j0 + 8 * tx];
        float4 v0, v1;
        v0.x = acc[i][0] + bi[0]; v0.y = acc[i][1] + bi[1];
        v0.z = acc[i][2] + bi[2]; v0.w = acc[i][3] + bi[3];
        v1.x = acc[i][4] + bi[4]; v1.y = acc[i][5] + bi[5];
        v1.z = acc[i][6] + bi[6]; v1.w = acc[i][7] + bi[7];
        *(float4*)(dst)     = v0;
        *(float4*)(dst + 4) = v1;
    }
}

// ---------------------------------------------------------------------------
// Kernel 2: recurrence + FC. 16 clusters x 8 CTAs x 512 threads.
// R3 structure (best measured): per-step compute -> psum reduce -> scalar
// DSMEM pushes -> one barrier.cluster. Inner product packed as fma.rn.f32x2,
// 2-step unroll for compile-time buffer indices.
// h layout hs[buf][srcRank][row][64]; compute loads are warp-broadcast LDS.
// ---------------------------------------------------------------------------
#define RNN_STEP(T, RB, WB)                                                   \
do {                                                                          \
    float xwv = 0.0f;                                                         \
    if (tid < 256)                                                            \
        xwv = g_xw[((size_t)(T) * BATCH + (r0 + rr)) * HID + j0 + jj];        \
    _Pragma("unroll")                                                         \
    for (int r = 0; r < RPC; ++r) {                                           \
        const ulonglong2* hrow = (const ulonglong2*)(&hs[RB][kc][r][0]);      \
        unsigned long long a0 = 0ull, a1 = 0ull;                              \
        _Pragma("unroll")                                                     \
        for (int q = 0; q < 16; ++q) {                                        \
            ulonglong2 hv = hrow[q];                                          \
            a0 = fma2(hv.x, wp[2*q],   a0);                                   \
            a1 = fma2(hv.y, wp[2*q+1], a1);                                   \
        }                                                                     \
        psum[r][kc][j] = f32x2_hsum(a0, a1);                                  \
    }                                                                         \
    __syncthreads();                                                          \
    if (tid < 256) {                                                          \
        float z = bhh + xwv;                                                  \
        _Pragma("unroll")                                                     \
        for (int c = 0; c < 8; ++c) z += psum[rr][c][jj];                     \
        const float hval = tanh_accurate(z);                                  \
        const uint32_t laddr = hsA +                                          \
            (uint32_t)((((WB) * CLUSTER + rank) * RPC + rr) * 64 + jj) * 4u;  \
        _Pragma("unroll")                                                     \
        for (int c = 0; c < CLUSTER; ++c)                                     \
            st_dsmem_f32(laddr, c, hval);                                     \
    }                                                                         \
    asm volatile("barrier.cluster.arrive.aligned;" ::: "memory");             \
    asm volatile("barrier.cluster.wait.aligned;"   ::: "memory");             \
} while (0)

__global__ void __cluster_dims__(CLUSTER, 1, 1) __launch_bounds__(512, 1)
rec_kernel(const float* __restrict__ W_hh,
           const float* __restrict__ b_hh,
           const float* __restrict__ W_fc,
           const float* __restrict__ b_fc,
           float* __restrict__ out)
{
    __shared__ __align__(16) float hs[2][CLUSTER][RPC][64];   // 16 KB
    __shared__ __align__(16) float psum[RPC][8][64];          // 8 KB

    const int tid  = threadIdx.x;
    const int rank = blockIdx.x & (CLUSTER - 1);
    const int cl   = blockIdx.x / CLUSTER;
    const int r0 = cl * RPC;
    const int j0 = rank * CPC;

    const int j  = tid & 63;    // compute: column within slice
    const int kc = tid >> 6;    // compute: 64-wide k chunk (0..7)
    const int rr = tid >> 6;    // reduce (tid<256): row 0..3
    const int jj = tid & 63;    // reduce: column

    const uint32_t hsA = smem_u32(hs);

    // W_hh slice packed as f32x2 pairs (64 floats = 32 u64), reused 256 steps.
    unsigned long long wp[32];
    {
        const float* wrow = W_hh + (size_t)(j0 + j) * HID + kc * 64;
#pragma unroll
        for (int q = 0; q < 16; ++q) {
            ulonglong2 v = *(const ulonglong2*)(wrow + 4 * q);
            wp[2*q]   = v.x;
            wp[2*q+1] = v.y;
        }
    }
    const float bhh = b_hh[j0 + jj];

    // h0 = 0 in buffer 0.
    for (int i = tid; i < CLUSTER * RPC * 64; i += 512)
        (&hs[0][0][0][0])[i] = 0.0f;
    __syncthreads();
    asm volatile("barrier.cluster.arrive.aligned;" ::: "memory");
    asm volatile("barrier.cluster.wait.aligned;"   ::: "memory");

    // 256 steps, unrolled in pairs: even step reads buf0/writes buf1, odd
    // step reads buf1/writes buf0.
#pragma unroll 1
    for (int q = 0; q < 128; ++q) {
        RNN_STEP(2 * q,     0, 1);
        RNN_STEP(2 * q + 1, 1, 0);
    }

    // FC: h_T in hs[0]; h[r][k] = hs[0][k>>6][r][k&63]. Warp w: r=w>>2, o=w&3.
    if (rank == 0) {
        const int w    = tid >> 5;
        const int lane = tid & 31;
        const int r = w >> 2;
        const int o = w & 3;
        float s = 0.0f;
        const float* wf = W_fc + (size_t)o * HID;
#pragma unroll
        for (int k = lane; k < HID; k += 32)
            s += hs[0][k >> 6][r][k & 63] * wf[k];
#pragma unroll
        for (int sh = 16; sh > 0; sh >>= 1)
            s += __shfl_xor_sync(0xFFFFFFFFu, s, sh);
        if (lane == 0)
            out[(r0 + r) * OUTD + o] = s + b_fc[o];
    }

    // Cluster-wide quiesce before exit (DSMEM lifetime).
    asm volatile("barrier.cluster.arrive.aligned;" ::: "memory");
    asm volatile("barrier.cluster.wait.aligned;"   ::: "memory");
}

extern "C" void kernel_launch(void* const* d_in, const int* in_sizes, int n_in,
                              void* d_out, int out_size)
{
    const int*   x    = (const int*)  d_in[0];
    const float* emb  = (const float*)d_in[1];
    const float* W_ih = (const float*)d_in[2];
    const float* W_hh = (const float*)d_in[3];
    const float* b_ih = (const float*)d_in[4];
    const float* b_hh = (const float*)d_in[5];
    const float* W_fc = (const float*)d_in[6];
    const float* b_fc = (const float*)d_in[7];
    float* out = (float*)d_out;
    (void)in_sizes; (void)n_in; (void)out_size;

    proj_kernel<<<dim3(HID / 128, (BATCH * T_STEPS) / 128), 256>>>(x, emb, W_ih, b_ih);
    rec_kernel<<<(BATCH / RPC) * CLUSTER, 512>>>(W_hh, b_hh, W_fc, b_fc, out);
}

// round 10
// speedup vs baseline: 1.7929x; 1.1159x over previous
#include <cuda_runtime.h>
#include <cstdint>

#define T_STEPS 256
#define BATCH   64
#define HID     512
#define OUTD    4

#define CLUSTER 8          // CTAs per cluster
#define RPC     4          // batch rows per cluster
#define CPC     64         // hidden columns per CTA

// Global scratch (no cudaMalloc allowed)
__device__ __align__(16) float g_xw[T_STEPS * BATCH * HID];   // [T][B][H]

__device__ __forceinline__ uint32_t smem_u32(const void* p) {
    uint32_t a;
    asm("{ .reg .u64 t; cvta.to.shared.u64 t, %1; cvt.u32.u64 %0, t; }"
        : "=r"(a) : "l"(p));
    return a;
}
__device__ __forceinline__ uint32_t mapa32(uint32_t a, int r) {
    uint32_t ra;
    asm("mapa.shared::cluster.u32 %0, %1, %2;" : "=r"(ra) : "r"(a), "r"(r));
    return ra;
}
__device__ __forceinline__ void mbar_init(uint32_t a, uint32_t cnt) {
    asm volatile("mbarrier.init.shared.b64 [%0], %1;" :: "r"(a), "r"(cnt) : "memory");
}
// Local arrive + expect_tx (consumer announces inbound bytes for this phase).
__device__ __forceinline__ void mbar_expect(uint32_t a, uint32_t bytes) {
    asm volatile("mbarrier.arrive.expect_tx.shared.b64 _, [%0], %1;"
                 :: "r"(a), "r"(bytes) : "memory");
}
// One-way remote store that signals the remote mbarrier's tx count.
__device__ __forceinline__ void st_async_f32(uint32_t rdst, float v, uint32_t rbar) {
    asm volatile("st.async.shared::cluster.mbarrier::complete_tx::bytes.b32 [%0], %1, [%2];"
                 :: "r"(rdst), "r"(__float_as_uint(v)), "r"(rbar) : "memory");
}
__device__ __forceinline__ void mbar_wait(uint32_t a, uint32_t parity) {
    asm volatile("{\n\t.reg .pred P;\n\t"
                 "WL%=:\n\t"
                 "mbarrier.try_wait.parity.acquire.cluster.shared::cta.b64 P, [%0], %1;\n\t"
                 "@P bra WD%=;\n\t"
                 "bra WL%=;\n\t"
                 "WD%=:\n\t}"
                 :: "r"(a), "r"(parity) : "memory");
}
__device__ __forceinline__ unsigned long long fma2(unsigned long long a,
                                                   unsigned long long b,
                                                   unsigned long long c) {
    unsigned long long d;
    asm("fma.rn.f32x2 %0, %1, %2, %3;" : "=l"(d) : "l"(a), "l"(b), "l"(c));
    return d;
}
__device__ __forceinline__ float f32x2_hsum(unsigned long long a,
                                            unsigned long long b) {
    unsigned long long s;
    asm("add.rn.f32x2 %0, %1, %2;" : "=l"(s) : "l"(a), "l"(b));
    unsigned int lo, hi;
    asm("mov.b64 {%0, %1}, %2;" : "=r"(lo), "=r"(hi) : "l"(s));
    return __uint_as_float(lo) + __uint_as_float(hi);
}

// Accurate even under --use_fast_math (expf -> __expf ~2^-21 rel error).
__device__ __forceinline__ float tanh_accurate(float z) {
    return 1.0f - 2.0f / (expf(2.0f * z) + 1.0f);
}

// ---------------------------------------------------------------------------
// Kernel 1: g_xw[t][b][:] = emb[x[b][t]] @ W_ih^T + b_ih
// 128x128 tile, BK=8, 256 threads, 8x8 microtile, register-prefetch pipeline.
// ---------------------------------------------------------------------------
__global__ void __launch_bounds__(256)
proj_kernel(const int* __restrict__ x,
            const float* __restrict__ emb,
            const float* __restrict__ W_ih,
            const float* __restrict__ b_ih)
{
    __shared__ float As[8][128];
    __shared__ float Bs[8][128];
    __shared__ int   idx[128];

    const int tid = threadIdx.x;
    const int m0 = blockIdx.y * 128;
    const int j0 = blockIdx.x * 128;

    if (tid < 128) idx[tid] = x[m0 + tid];
    __syncthreads();

    const int lrow = tid >> 1;
    const int lq   = tid & 1;
    const int ty = tid >> 4;
    const int tx = tid & 15;

    const size_t arow = (size_t)idx[lrow] * HID;
    const size_t brow = (size_t)(j0 + lrow) * HID;

    float acc[8][8];
#pragma unroll
    for (int i = 0; i < 8; ++i)
#pragma unroll
        for (int jc = 0; jc < 8; ++jc) acc[i][jc] = 0.0f;

    float4 av = *(const float4*)(emb  + arow + 4 * lq);
    float4 bv = *(const float4*)(W_ih + brow + 4 * lq);

    for (int k0 = 0; k0 < HID; k0 += 8) {
        As[4*lq+0][lrow] = av.x; As[4*lq+1][lrow] = av.y;
        As[4*lq+2][lrow] = av.z; As[4*lq+3][lrow] = av.w;
        Bs[4*lq+0][lrow] = bv.x; Bs[4*lq+1][lrow] = bv.y;
        Bs[4*lq+2][lrow] = bv.z; Bs[4*lq+3][lrow] = bv.w;
        __syncthreads();

        if (k0 + 8 < HID) {
            av = *(const float4*)(emb  + arow + k0 + 8 + 4 * lq);
            bv = *(const float4*)(W_ih + brow + k0 + 8 + 4 * lq);
        }

#pragma unroll
        for (int k = 0; k < 8; ++k) {
            float a[8], b[8];
            *(float4*)(a)     = *(const float4*)(&As[k][8 * ty]);
            *(float4*)(a + 4) = *(const float4*)(&As[k][8 * ty + 4]);
            *(float4*)(b)     = *(const float4*)(&Bs[k][8 * tx]);
            *(float4*)(b + 4) = *(const float4*)(&Bs[k][8 * tx + 4]);
#pragma unroll
            for (int i = 0; i < 8; ++i)
#pragma unroll
                for (int jc = 0; jc < 8; ++jc)
                    acc[i][jc] += a[i] * b[jc];
        }
        __syncthreads();
    }

    float bi[8];
    *(float4*)(bi)     = *(const float4*)(b_ih + j0 + 8 * tx);
    *(float4*)(bi + 4) = *(const float4*)(b_ih + j0 + 8 * tx + 4);

#pragma unroll
    for (int i = 0; i < 8; ++i) {
        int m = m0 + 8 * ty + i;
        int b = m >> 8;      // T = 256
        int t = m & 255;
        float* dst = &g_xw[((size_t)t * BATCH + b) * HID + j0 + 8 * tx];
        float4 v0, v1;
        v0.x = acc[i][0] + bi[0]; v0.y = acc[i][1] + bi[1];
        v0.z = acc[i][2] + bi[2]; v0.w = acc[i][3] + bi[3];
        v1.x = acc[i][4] + bi[4]; v1.y = acc[i][5] + bi[5];
        v1.z = acc[i][6] + bi[6]; v1.w = acc[i][7] + bi[7];
        *(float4*)(dst)     = v0;
        *(float4*)(dst + 4) = v1;
    }
}

// ---------------------------------------------------------------------------
// Kernel 2: recurrence + FC. 16 clusters x 8 CTAs x 512 threads.
// Exchange: one-way st.async pushes with mbarrier tx accounting.
// Per step: tid0 pre-announces 8KB inbound on bar[wb]; all threads wait
// bar[rb] (includes own pushes -> read-release for the double buffer);
// compute (f32x2) -> psum -> reduce -> tanh -> 8x st.async to peers.
// No barrier.cluster, no fences in the loop. Max cross-CTA skew = 1 step,
// race-free by the own-stores-after-own-reads argument.
// ---------------------------------------------------------------------------
#define RNN_STEP(T, RB, WB, PHVAR, DOWAIT)                                    \
do {                                                                          \
    if (tid == 0) mbar_expect(barA + 8 * (WB), 8192u);                        \
    float xwv = 0.0f;                                                         \
    if (tid < 256)                                                            \
        xwv = g_xw[((size_t)(T) * BATCH + (r0 + rr)) * HID + j0 + jj];        \
    if (DOWAIT) { mbar_wait(barA + 8 * (RB), PHVAR); PHVAR ^= 1u; }           \
    _Pragma("unroll")                                                         \
    for (int r = 0; r < RPC; ++r) {                                           \
        const ulonglong2* hrow = (const ulonglong2*)(&hs[RB][kc][r][0]);      \
        unsigned long long a0 = 0ull, a1 = 0ull;                              \
        _Pragma("unroll")                                                     \
        for (int q = 0; q < 16; ++q) {                                        \
            ulonglong2 hv = hrow[q];                                          \
            a0 = fma2(hv.x, wp[2*q],   a0);                                   \
            a1 = fma2(hv.y, wp[2*q+1], a1);                                   \
        }                                                                     \
        psum[r][kc][j] = f32x2_hsum(a0, a1);                                  \
    }                                                                         \
    __syncthreads();                                                          \
    if (tid < 256) {                                                          \
        float z = bhh + xwv;                                                  \
        _Pragma("unroll")                                                     \
        for (int c = 0; c < 8; ++c) z += psum[rr][c][jj];                     \
        const float hval = tanh_accurate(z);                                  \
        const uint32_t loff = hsA +                                           \
            (uint32_t)((((WB) * CLUSTER + rank) * RPC + rr) * 64 + jj) * 4u;  \
        const uint32_t lbar = barA + 8 * (WB);                                \
        _Pragma("unroll")                                                     \
        for (int c = 0; c < CLUSTER; ++c)                                     \
            st_async_f32(mapa32(loff, c), hval, mapa32(lbar, c));             \
    }                                                                         \
} while (0)

__global__ void __cluster_dims__(CLUSTER, 1, 1) __launch_bounds__(512, 1)
rec_kernel(const float* __restrict__ W_hh,
           const float* __restrict__ b_hh,
           const float* __restrict__ W_fc,
           const float* __restrict__ b_fc,
           float* __restrict__ out)
{
    __shared__ __align__(16) float hs[2][CLUSTER][RPC][64];   // 16 KB
    __shared__ __align__(16) float psum[RPC][8][64];          // 8 KB
    __shared__ __align__(8)  unsigned long long mbar[2];

    const int tid  = threadIdx.x;
    const int rank = blockIdx.x & (CLUSTER - 1);
    const int cl   = blockIdx.x / CLUSTER;
    const int r0 = cl * RPC;
    const int j0 = rank * CPC;

    const int j  = tid & 63;    // compute: column within slice
    const int kc = tid >> 6;    // compute: 64-wide k chunk (0..7)
    const int rr = tid >> 6;    // reduce (tid<256): row 0..3
    const int jj = tid & 63;    // reduce: column

    const uint32_t hsA  = smem_u32(hs);
    const uint32_t barA = smem_u32(mbar);

    // W_hh slice packed as f32x2 pairs (64 floats = 32 u64), reused 256 steps.
    unsigned long long wp[32];
    {
        const float* wrow = W_hh + (size_t)(j0 + j) * HID + kc * 64;
#pragma unroll
        for (int q = 0; q < 16; ++q) {
            ulonglong2 v = *(const ulonglong2*)(wrow + 4 * q);
            wp[2*q]   = v.x;
            wp[2*q+1] = v.y;
        }
    }
    const float bhh = b_hh[j0 + jj];

    // Init: two mbarriers (1 arrival each = tid0's expect_tx) + h0 = 0.
    if (tid == 0) { mbar_init(barA, 1u); mbar_init(barA + 8, 1u); }
    for (int i = tid; i < CLUSTER * RPC * 64; i += 512)
        (&hs[0][0][0][0])[i] = 0.0f;
    __syncthreads();
    // Peers' barriers must be initialized before any st.async reaches them.
    asm volatile("barrier.cluster.arrive.aligned;" ::: "memory");
    asm volatile("barrier.cluster.wait.aligned;"   ::: "memory");

    uint32_t ph0 = 0, ph1 = 0;

    // Step 1: reads local zeros in hs[0] (no wait), writes hs[1]/bar1.
    RNN_STEP(0, 0, 1, ph1, false);
    // Step 2: waits bar1, writes hs[0]/bar0.
    RNN_STEP(1, 1, 0, ph1, true);
    // Steps 3..256 in pairs.
#pragma unroll 1
    for (int q = 1; q < 128; ++q) {
        RNN_STEP(2 * q,     0, 1, ph0, true);   // odd step
        RNN_STEP(2 * q + 1, 1, 0, ph1, true);   // even step
    }

    // Consume the step-256 pushes (buffer 0).
    mbar_wait(barA, ph0);

    // FC: h_T in hs[0]; h[r][k] = hs[0][k>>6][r][k&63]. Warp w: r=w>>2, o=w&3.
    if (rank == 0) {
        const int w    = tid >> 5;
        const int lane = tid & 31;
        const int r = w >> 2;
        const int o = w & 3;
        float s = 0.0f;
        const float* wf = W_fc + (size_t)o * HID;
#pragma unroll
        for (int k = lane; k < HID; k += 32)
            s += hs[0][k >> 6][r][k & 63] * wf[k];
#pragma unroll
        for (int sh = 16; sh > 0; sh >>= 1)
            s += __shfl_xor_sync(0xFFFFFFFFu, s, sh);
        if (lane == 0)
            out[(r0 + r) * OUTD + o] = s + b_fc[o];
    }

    // Cluster-wide quiesce before exit (DSMEM lifetime).
    asm volatile("barrier.cluster.arrive.aligned;" ::: "memory");
    asm volatile("barrier.cluster.wait.aligned;"   ::: "memory");
}

extern "C" void kernel_launch(void* const* d_in, const int* in_sizes, int n_in,
                              void* d_out, int out_size)
{
    const int*   x    = (const int*)  d_in[0];
    const float* emb  = (const float*)d_in[1];
    const float* W_ih = (const float*)d_in[2];
    const float* W_hh = (const float*)d_in[3];
    const float* b_ih = (const float*)d_in[4];
    const float* b_hh = (const float*)d_in[5];
    const float* W_fc = (const float*)d_in[6];
    const float* b_fc = (const float*)d_in[7];
    float* out = (float*)d_out;
    (void)in_sizes; (void)n_in; (void)out_size;

    proj_kernel<<<dim3(HID / 128, (BATCH * T_STEPS) / 128), 256>>>(x, emb, W_ih, b_ih);
    rec_kernel<<<(BATCH / RPC) * CLUSTER, 512>>>(W_hh, b_hh, W_fc, b_fc, out);
}

// round 11
// speedup vs baseline: 2.0322x; 1.1335x over previous
#include <cuda_runtime.h>
#include <cstdint>

#define T_STEPS 256
#define BATCH   64
#define HID     512
#define OUTD    4

#define CLUSTER 8          // CTAs per cluster
#define RPC     4          // batch rows per cluster
#define CPC     64         // hidden columns per CTA

// Global scratch (no cudaMalloc allowed)
__device__ __align__(16) float g_xw[T_STEPS * BATCH * HID];   // [T][B][H]

__device__ __forceinline__ uint32_t smem_u32(const void* p) {
    uint32_t a;
    asm("{ .reg .u64 t; cvta.to.shared.u64 t, %1; cvt.u32.u64 %0, t; }"
        : "=r"(a) : "l"(p));
    return a;
}
__device__ __forceinline__ uint32_t mapa32(uint32_t a, int r) {
    uint32_t ra;
    asm("mapa.shared::cluster.u32 %0, %1, %2;" : "=r"(ra) : "r"(a), "r"(r));
    return ra;
}
__device__ __forceinline__ void mbar_init(uint32_t a, uint32_t cnt) {
    asm volatile("mbarrier.init.shared.b64 [%0], %1;" :: "r"(a), "r"(cnt) : "memory");
}
__device__ __forceinline__ void mbar_expect(uint32_t a, uint32_t bytes) {
    asm volatile("mbarrier.arrive.expect_tx.shared.b64 _, [%0], %1;"
                 :: "r"(a), "r"(bytes) : "memory");
}
// One-way remote 8-byte store that signals the remote mbarrier's tx count.
__device__ __forceinline__ void st_async_b64(uint32_t rdst, unsigned long long v,
                                             uint32_t rbar) {
    asm volatile("st.async.shared::cluster.mbarrier::complete_tx::bytes.b64 [%0], %1, [%2];"
                 :: "r"(rdst), "l"(v), "r"(rbar) : "memory");
}
__device__ __forceinline__ void mbar_wait(uint32_t a, uint32_t parity) {
    asm volatile("{\n\t.reg .pred P;\n\t"
                 "WL%=:\n\t"
                 "mbarrier.try_wait.parity.acquire.cluster.shared::cta.b64 P, [%0], %1;\n\t"
                 "@P bra WD%=;\n\t"
                 "bra WL%=;\n\t"
                 "WD%=:\n\t}"
                 :: "r"(a), "r"(parity) : "memory");
}
__device__ __forceinline__ unsigned long long fma2(unsigned long long a,
                                                   unsigned long long b,
                                                   unsigned long long c) {
    unsigned long long d;
    asm("fma.rn.f32x2 %0, %1, %2, %3;" : "=l"(d) : "l"(a), "l"(b), "l"(c));
    return d;
}
__device__ __forceinline__ float f32x2_hsum(unsigned long long a,
                                            unsigned long long b) {
    unsigned long long s;
    asm("add.rn.f32x2 %0, %1, %2;" : "=l"(s) : "l"(a), "l"(b));
    unsigned int lo, hi;
    asm("mov.b64 {%0, %1}, %2;" : "=r"(lo), "=r"(hi) : "l"(s));
    return __uint_as_float(lo) + __uint_as_float(hi);
}
__device__ __forceinline__ unsigned long long pack2(float x, float y) {
    unsigned long long v;
    asm("mov.b64 %0, {%1, %2};" : "=l"(v) : "r"(__float_as_uint(x)), "r"(__float_as_uint(y)));
    return v;
}

// Accurate even under --use_fast_math (expf -> __expf ~2^-21 rel error).
__device__ __forceinline__ float tanh_accurate(float z) {
    return 1.0f - 2.0f / (expf(2.0f * z) + 1.0f);
}

// ---------------------------------------------------------------------------
// Kernel 1: g_xw[t][b][:] = emb[x[b][t]] @ W_ih^T + b_ih
// 128x128 tile, BK=8, 256 threads, 8x8 microtile, register-prefetch pipeline.
// ---------------------------------------------------------------------------
__global__ void __launch_bounds__(256)
proj_kernel(const int* __restrict__ x,
            const float* __restrict__ emb,
            const float* __restrict__ W_ih,
            const float* __restrict__ b_ih)
{
    __shared__ float As[8][128];
    __shared__ float Bs[8][128];
    __shared__ int   idx[128];

    const int tid = threadIdx.x;
    const int m0 = blockIdx.y * 128;
    const int j0 = blockIdx.x * 128;

    if (tid < 128) idx[tid] = x[m0 + tid];
    __syncthreads();

    const int lrow = tid >> 1;
    const int lq   = tid & 1;
    const int ty = tid >> 4;
    const int tx = tid & 15;

    const size_t arow = (size_t)idx[lrow] * HID;
    const size_t brow = (size_t)(j0 + lrow) * HID;

    float acc[8][8];
#pragma unroll
    for (int i = 0; i < 8; ++i)
#pragma unroll
        for (int jc = 0; jc < 8; ++jc) acc[i][jc] = 0.0f;

    float4 av = *(const float4*)(emb  + arow + 4 * lq);
    float4 bv = *(const float4*)(W_ih + brow + 4 * lq);

    for (int k0 = 0; k0 < HID; k0 += 8) {
        As[4*lq+0][lrow] = av.x; As[4*lq+1][lrow] = av.y;
        As[4*lq+2][lrow] = av.z; As[4*lq+3][lrow] = av.w;
        Bs[4*lq+0][lrow] = bv.x; Bs[4*lq+1][lrow] = bv.y;
        Bs[4*lq+2][lrow] = bv.z; Bs[4*lq+3][lrow] = bv.w;
        __syncthreads();

        if (k0 + 8 < HID) {
            av = *(const float4*)(emb  + arow + k0 + 8 + 4 * lq);
            bv = *(const float4*)(W_ih + brow + k0 + 8 + 4 * lq);
        }

#pragma unroll
        for (int k = 0; k < 8; ++k) {
            float a[8], b[8];
            *(float4*)(a)     = *(const float4*)(&As[k][8 * ty]);
            *(float4*)(a + 4) = *(const float4*)(&As[k][8 * ty + 4]);
            *(float4*)(b)     = *(const float4*)(&Bs[k][8 * tx]);
            *(float4*)(b + 4) = *(const float4*)(&Bs[k][8 * tx + 4]);
#pragma unroll
            for (int i = 0; i < 8; ++i)
#pragma unroll
                for (int jc = 0; jc < 8; ++jc)
                    acc[i][jc] += a[i] * b[jc];
        }
        __syncthreads();
    }

    float bi[8];
    *(float4*)(bi)     = *(const float4*)(b_ih + j0 + 8 * tx);
    *(float4*)(bi + 4) = *(const float4*)(b_ih + j0 + 8 * tx + 4);

#pragma unroll
    for (int i = 0; i < 8; ++i) {
        int m = m0 + 8 * ty + i;
        int b = m >> 8;      // T = 256
        int t = m & 255;
        float* dst = &g_xw[((size_t)t * BATCH + b) * HID + j0 + 8 * tx];
        float4 v0, v1;
        v0.x = acc[i][0] + bi[0]; v0.y = acc[i][1] + bi[1];
        v0.z = acc[i][2] + bi[2]; v0.w = acc[i][3] + bi[3];
        v1.x = acc[i][4] + bi[4]; v1.y = acc[i][5] + bi[5];
        v1.z = acc[i][6] + bi[6]; v1.w = acc[i][7] + bi[7];
        *(float4*)(dst)     = v0;
        *(float4*)(dst + 4) = v1;
    }
}

// ---------------------------------------------------------------------------
// Kernel 2: recurrence + FC. 16 clusters x 8 CTAs x 512 threads.
// Compute: thread (j2 = tid&31 -> cols 2j2,2j2+1; kc = tid>>5 -> 32-wide k
// chunk). Both columns share the same h registers -> LDS halved vs 1-col map.
// Reduce: 128 threads, 2 cols each; pushes are st.async.b64 (8 per thread).
// Per-step sync: tid0 expect_tx(8KB) on bar[wb]; all threads parity-wait
// bar[rb] (includes own pushes -> read-release for the double buffer).
// ---------------------------------------------------------------------------
#define RNN_STEP(T, RB, WB, PHVAR, DOWAIT)                                    \
do {                                                                          \
    if (tid == 0) mbar_expect(barA + 8 * (WB), 8192u);                        \
    float2 xw2 = make_float2(0.0f, 0.0f);                                     \
    if (tid < 128)                                                            \
        xw2 = *(const float2*)&g_xw[((size_t)(T) * BATCH + (r0 + rr)) * HID   \
                                    + j0 + 2 * jj2];                          \
    if (DOWAIT) { mbar_wait(barA + 8 * (RB), PHVAR); PHVAR ^= 1u; }           \
    _Pragma("unroll")                                                         \
    for (int r = 0; r < RPC; ++r) {                                           \
        const ulonglong2* hrow = (const ulonglong2*)                          \
            (&hs[RB][kc >> 1][r][(kc & 1) * 32]);                             \
        unsigned long long a0 = 0ull, b0 = 0ull, a1 = 0ull, b1 = 0ull;        \
        _Pragma("unroll")                                                     \
        for (int q = 0; q < 8; ++q) {                                         \
            ulonglong2 hv = hrow[q];                                          \
            a0 = fma2(hv.x, wp0[2*q],   a0);                                  \
            b0 = fma2(hv.y, wp0[2*q+1], b0);                                  \
            a1 = fma2(hv.x, wp1[2*q],   a1);                                  \
            b1 = fma2(hv.y, wp1[2*q+1], b1);                                  \
        }                                                                     \
        *(float2*)&psum[r][kc][2 * j2] =                                      \
            make_float2(f32x2_hsum(a0, b0), f32x2_hsum(a1, b1));              \
    }                                                                         \
    __syncthreads();                                                          \
    if (tid < 128) {                                                          \
        float z0 = bhh2.x + xw2.x;                                            \
        float z1 = bhh2.y + xw2.y;                                            \
        _Pragma("unroll")                                                     \
        for (int c = 0; c < 16; ++c) {                                        \
            float2 pv = *(const float2*)&psum[rr][c][2 * jj2];                \
            z0 += pv.x; z1 += pv.y;                                           \
        }                                                                     \
        const unsigned long long hpk =                                        \
            pack2(tanh_accurate(z0), tanh_accurate(z1));                      \
        const uint32_t loff = hsA +                                           \
            (uint32_t)((((WB) * CLUSTER + rank) * RPC + rr) * 64 + 2 * jj2)   \
            * 4u;                                                             \
        const uint32_t lbar = barA + 8 * (WB);                                \
        _Pragma("unroll")                                                     \
        for (int c = 0; c < CLUSTER; ++c)                                     \
            st_async_b64(mapa32(loff, c), hpk, mapa32(lbar, c));              \
    }                                                                         \
} while (0)

__global__ void __cluster_dims__(CLUSTER, 1, 1) __launch_bounds__(512, 1)
rec_kernel(const float* __restrict__ W_hh,
           const float* __restrict__ b_hh,
           const float* __restrict__ W_fc,
           const float* __restrict__ b_fc,
           float* __restrict__ out)
{
    __shared__ __align__(16) float hs[2][CLUSTER][RPC][64];   // 16 KB
    __shared__ __align__(16) float psum[RPC][16][64];         // 16 KB
    __shared__ __align__(8)  unsigned long long mbar[2];

    const int tid  = threadIdx.x;
    const int rank = blockIdx.x & (CLUSTER - 1);
    const int cl   = blockIdx.x / CLUSTER;
    const int r0 = cl * RPC;
    const int j0 = rank * CPC;

    const int j2  = tid & 31;   // compute: column pair (cols 2j2, 2j2+1)
    const int kc  = tid >> 5;   // compute: 32-wide k chunk (0..15)
    const int rr  = tid >> 5;   // reduce (tid<128): row 0..3
    const int jj2 = tid & 31;   // reduce: column pair

    const uint32_t hsA  = smem_u32(hs);
    const uint32_t barA = smem_u32(mbar);

    // W_hh slices for 2 columns, packed as f32x2 k-pairs (16 u64 each).
    unsigned long long wp0[16], wp1[16];
    {
        const float* w0 = W_hh + (size_t)(j0 + 2 * j2)     * HID + kc * 32;
        const float* w1 = W_hh + (size_t)(j0 + 2 * j2 + 1) * HID + kc * 32;
#pragma unroll
        for (int q = 0; q < 8; ++q) {
            ulonglong2 v0 = *(const ulonglong2*)(w0 + 4 * q);
            ulonglong2 v1 = *(const ulonglong2*)(w1 + 4 * q);
            wp0[2*q] = v0.x; wp0[2*q+1] = v0.y;
            wp1[2*q] = v1.x; wp1[2*q+1] = v1.y;
        }
    }
    float2 bhh2 = make_float2(0.0f, 0.0f);
    if (tid < 128) bhh2 = *(const float2*)&b_hh[j0 + 2 * jj2];

    // Init: two mbarriers (1 arrival each = tid0's expect_tx) + h0 = 0.
    if (tid == 0) { mbar_init(barA, 1u); mbar_init(barA + 8, 1u); }
    for (int i = tid; i < CLUSTER * RPC * 64; i += 512)
        (&hs[0][0][0][0])[i] = 0.0f;
    __syncthreads();
    // Peers' barriers must be initialized before any st.async reaches them.
    asm volatile("barrier.cluster.arrive.aligned;" ::: "memory");
    asm volatile("barrier.cluster.wait.aligned;"   ::: "memory");

    uint32_t ph0 = 0, ph1 = 0;

    // Step 1: reads local zeros in hs[0] (no wait), writes hs[1]/bar1.
    RNN_STEP(0, 0, 1, ph1, false);
    // Step 2: waits bar1, writes hs[0]/bar0.
    RNN_STEP(1, 1, 0, ph1, true);
    // Steps 3..256 in pairs.
#pragma unroll 1
    for (int q = 1; q < 128; ++q) {
        RNN_STEP(2 * q,     0, 1, ph0, true);   // odd step
        RNN_STEP(2 * q + 1, 1, 0, ph1, true);   // even step
    }

    // Consume the step-256 pushes (buffer 0).
    mbar_wait(barA, ph0);

    // FC: h_T in hs[0]; h[r][k] = hs[0][k>>6][r][k&63]. Warp w: r=w>>2, o=w&3.
    if (rank == 0) {
        const int w    = tid >> 5;
        const int lane = tid & 31;
        const int r = w >> 2;
        const int o = w & 3;
        float s = 0.0f;
        const float* wf = W_fc + (size_t)o * HID;
#pragma unroll
        for (int k = lane; k < HID; k += 32)
            s += hs[0][k >> 6][r][k & 63] * wf[k];
#pragma unroll
        for (int sh = 16; sh > 0; sh >>= 1)
            s += __shfl_xor_sync(0xFFFFFFFFu, s, sh);
        if (lane == 0)
            out[(r0 + r) * OUTD + o] = s + b_fc[o];
    }

    // Cluster-wide quiesce before exit (DSMEM lifetime).
    asm volatile("barrier.cluster.arrive.aligned;" ::: "memory");
    asm volatile("barrier.cluster.wait.aligned;"   ::: "memory");
}

extern "C" void kernel_launch(void* const* d_in, const int* in_sizes, int n_in,
                              void* d_out, int out_size)
{
    const int*   x    = (const int*)  d_in[0];
    const float* emb  = (const float*)d_in[1];
    const float* W_ih = (const float*)d_in[2];
    const float* W_hh = (const float*)d_in[3];
    const float* b_ih = (const float*)d_in[4];
    const float* b_hh = (const float*)d_in[5];
    const float* W_fc = (const float*)d_in[6];
    const float* b_fc = (const float*)d_in[7];
    float* out = (float*)d_out;
    (void)in_sizes; (void)n_in; (void)out_size;

    proj_kernel<<<dim3(HID / 128, (BATCH * T_STEPS) / 128), 256>>>(x, emb, W_ih, b_ih);
    rec_kernel<<<(BATCH / RPC) * CLUSTER, 512>>>(W_hh, b_hh, W_fc, b_fc, out);
}